// round 11
// baseline (speedup 1.0000x reference)
#include <cuda_runtime.h>
#include <cuda_bf16.h>

#define N_NODES 100000
#define N_EDGES 1600000
#define N_FEAT  602
#define HIDDEN  128
#define N_CLS   41

// ---------------- scratch (static device globals; no runtime alloc) ----------
__device__ float g_h[(long)N_NODES * HIDDEN];      // GEMM1 output (pre-agg messages)
__device__ float g_h1[(long)N_NODES * HIDDEN];     // layer-1 output (post relu)
__device__ float g_msg2[(long)N_NODES * N_CLS];    // layer-2 projected messages
__device__ float g_norm_src[N_NODES];
__device__ float g_norm_dst[N_NODES];
__device__ int   g_deg_src[N_NODES];
__device__ int   g_deg_dst[N_NODES];
__device__ int   g_off[N_NODES + 1];               // CSR row offsets (by dst)
__device__ int   g_cursor[N_NODES];
__device__ int   g_csrc[N_EDGES];                  // src node per CSR slot

// ---------------- helpers ----------------------------------------------------
__device__ __forceinline__ unsigned f2tf(float f) {
    unsigned u;
    asm("cvt.rna.tf32.f32 %0, %1;" : "=r"(u) : "f"(f));
    return u;
}

__device__ __forceinline__ void mma_tf32(float d[4], const unsigned a[4], const unsigned b[2]) {
    asm volatile(
        "mma.sync.aligned.m16n8k8.row.col.f32.tf32.tf32.f32 "
        "{%0,%1,%2,%3}, {%4,%5,%6,%7}, {%8,%9}, {%0,%1,%2,%3};"
        : "+f"(d[0]), "+f"(d[1]), "+f"(d[2]), "+f"(d[3])
        : "r"(a[0]), "r"(a[1]), "r"(a[2]), "r"(a[3]),
          "r"(b[0]), "r"(b[1]));
}

__device__ __forceinline__ void cp_async8(unsigned smem_addr, const void* gptr, int src_bytes) {
    asm volatile("cp.async.ca.shared.global [%0], [%1], 8, %2;\n"
                 :: "r"(smem_addr), "l"(gptr), "r"(src_bytes));
}
__device__ __forceinline__ void cp_async16(unsigned smem_addr, const void* gptr, int src_bytes) {
    asm volatile("cp.async.ca.shared.global [%0], [%1], 16, %2;\n"
                 :: "r"(smem_addr), "l"(gptr), "r"(src_bytes));
}
__device__ __forceinline__ void cp_commit() {
    asm volatile("cp.async.commit_group;\n");
}
template<int N>
__device__ __forceinline__ void cp_wait() {
    asm volatile("cp.async.wait_group %0;\n" :: "n"(N));
}

// ---------------- init / degrees / norms -------------------------------------
__global__ void k_init() {
    int i = blockIdx.x * blockDim.x + threadIdx.x;
    if (i < N_NODES) { g_deg_src[i] = 0; g_deg_dst[i] = 0; }
}

__global__ void k_degrees(const int* __restrict__ src, const int* __restrict__ dst) {
    int i = blockIdx.x * blockDim.x + threadIdx.x;
    int e0 = i * 2;
    if (e0 < N_EDGES) {
        atomicAdd(&g_deg_src[__ldg(&src[e0])], 1);
        atomicAdd(&g_deg_dst[__ldg(&dst[e0])], 1);
    }
    int e1 = e0 + 1;
    if (e1 < N_EDGES) {
        atomicAdd(&g_deg_src[__ldg(&src[e1])], 1);
        atomicAdd(&g_deg_dst[__ldg(&dst[e1])], 1);
    }
}

__global__ void k_norms() {
    int i = blockIdx.x * blockDim.x + threadIdx.x;
    if (i < N_NODES) {
        g_norm_src[i] = rsqrtf((float)max(g_deg_src[i], 1));
        g_norm_dst[i] = rsqrtf((float)max(g_deg_dst[i], 1));
    }
}

// ---------------- exclusive scan of deg_dst -> off, cursor (1 block) ---------
#define SCAN_T 1024
__global__ __launch_bounds__(SCAN_T) void k_scan() {
    __shared__ int s_sum[SCAN_T];
    const int CH = (N_NODES + SCAN_T - 1) / SCAN_T;   // 98
    int t = threadIdx.x;
    int beg = t * CH;
    int end = min(beg + CH, N_NODES);
    int sum = 0;
#pragma unroll 4
    for (int i = beg; i < end; i++) sum += g_deg_dst[i];
    s_sum[t] = sum;
    __syncthreads();
    for (int off = 1; off < SCAN_T; off <<= 1) {
        int v = (t >= off) ? s_sum[t - off] : 0;
        __syncthreads();
        s_sum[t] += v;
        __syncthreads();
    }
    int run = s_sum[t] - sum;
#pragma unroll 4
    for (int i = beg; i < end; i++) {
        g_off[i] = run;
        g_cursor[i] = run;
        run += g_deg_dst[i];
    }
    if (t == SCAN_T - 1) g_off[N_NODES] = run;        // == N_EDGES
}

__global__ void k_fill(const int* __restrict__ src, const int* __restrict__ dst) {
    int i = blockIdx.x * blockDim.x + threadIdx.x;
    if (i < N_EDGES) {
        int pos = atomicAdd(&g_cursor[__ldg(&dst[i])], 1);
        g_csrc[pos] = __ldg(&src[i]);
    }
}

// ---------------- GEMM1 (tf32 mma + 3-stage cp.async pipeline) ---------------
// h = (x @ W1) * norm_src[row]  (norm folded into epilogue)
// 128x128x16 tile, 8 warps (4M x 2N), warp tile 32x64 = 2x8 m16n8k8 per k8.
// As[m][k] stride 20 (frag banks 20*qr+qc all distinct mod 32)
// Bs[k][n] stride 136 (frag banks 8*qc+qr all distinct mod 32)
#define BM 128
#define BN 128
#define BK 16
#define NT ((N_FEAT + BK - 1) / BK)   // 38
#define ASTRIDE (BK + 4)              // 20
#define BSTRIDE (BN + 8)              // 136
#define STAGES 3
#define A_ELEMS (BM * ASTRIDE)        // 2560 floats/stage
#define B_ELEMS (BK * BSTRIDE)        // 2176 floats/stage
#define G1_SMEM_BYTES (STAGES * (A_ELEMS + B_ELEMS) * 4)   // 56832

__global__ __launch_bounds__(256) void k_gemm1(
    const float* __restrict__ x, const float* __restrict__ W1,
    float* __restrict__ h)
{
    extern __shared__ __align__(16) float smem[];
    float (*As)[BM][ASTRIDE] = (float(*)[BM][ASTRIDE])smem;
    float (*Bs)[BK][BSTRIDE] = (float(*)[BK][BSTRIDE])(smem + STAGES * A_ELEMS);

    const int tid  = threadIdx.x;
    const int wid  = tid >> 5;
    const int lane = tid & 31;
    const int warp_m = wid & 3;
    const int warp_n = wid >> 2;
    const int row0 = blockIdx.x * BM;
    const int qr = lane >> 2;              // 0..7
    const int qc = lane & 3;               // 0..3

    float acc[2][8][4];
#pragma unroll
    for (int mi = 0; mi < 2; mi++)
#pragma unroll
        for (int ni = 0; ni < 8; ni++)
#pragma unroll
            for (int j = 0; j < 4; j++) acc[mi][ni][j] = 0.f;

    auto issue_tile = [&](int t, int s) {
        int k0 = t * BK;
#pragma unroll
        for (int i = 0; i < 4; i++) {
            int p = tid + i * 256;
            int r = p >> 3;                // 0..127
            int k2 = (p & 7) * 2;          // 0,2,..,14 (even)
            int gr = row0 + r;
            int kk = k0 + k2;              // even; N_FEAT even -> tail is 8B or nothing
            int nb = (gr < N_NODES && kk < N_FEAT) ? 8 : 0;
            const float* gp = x + (long)min(gr, N_NODES - 1) * N_FEAT + min(kk, N_FEAT - 2);
            unsigned d = (unsigned)__cvta_generic_to_shared(&As[s][r][k2]);
            cp_async8(d, gp, nb);
        }
#pragma unroll
        for (int i = 0; i < 2; i++) {
            int q = tid + i * 256;
            int k = q >> 5;                // 0..15
            int c4 = (q & 31) * 4;
            int gk = k0 + k;
            int nb = (gk < N_FEAT) ? 16 : 0;
            const float* gp = W1 + (long)min(gk, N_FEAT - 1) * HIDDEN + c4;
            unsigned d = (unsigned)__cvta_generic_to_shared(&Bs[s][k][c4]);
            cp_async16(d, gp, nb);
        }
        cp_commit();
    };

    issue_tile(0, 0);
    issue_tile(1, 1);

    for (int t = 0; t < NT; t++) {
        int s = t % STAGES;
        // keep 2 tiles in flight; buffer (t+2)%3 drained by end-of-(t-1) barrier
        if (t + 2 < NT) { issue_tile(t + 2, (t + 2) % STAGES); cp_wait<2>(); }
        else if (t + 1 < NT) { cp_wait<1>(); }
        else { cp_wait<0>(); }
        __syncthreads();

#pragma unroll
        for (int ks = 0; ks < BK; ks += 8) {
            unsigned bf[8][2];
#pragma unroll
            for (int ni = 0; ni < 8; ni++) {
                int n0 = warp_n * 64 + ni * 8;
                bf[ni][0] = f2tf(Bs[s][ks + qc][n0 + qr]);
                bf[ni][1] = f2tf(Bs[s][ks + qc + 4][n0 + qr]);
            }
#pragma unroll
            for (int mi = 0; mi < 2; mi++) {
                int m0 = warp_m * 32 + mi * 16;
                unsigned af[4];
                af[0] = f2tf(As[s][m0 + qr][ks + qc]);
                af[1] = f2tf(As[s][m0 + qr + 8][ks + qc]);
                af[2] = f2tf(As[s][m0 + qr][ks + qc + 4]);
                af[3] = f2tf(As[s][m0 + qr + 8][ks + qc + 4]);
#pragma unroll
                for (int ni = 0; ni < 8; ni++)
                    mma_tf32(acc[mi][ni], af, bf[ni]);
            }
        }
        __syncthreads();   // all reads of buffer s done before re-issue at t+1
    }

    // ---- epilogue: scale row by norm_src; c0,c1 @(qr,2qc), c2,c3 @(qr+8,2qc)
#pragma unroll
    for (int mi = 0; mi < 2; mi++) {
        int mbase = row0 + warp_m * 32 + mi * 16;
        int r0 = mbase + qr;
        int r1 = mbase + qr + 8;
        float ns0 = (r0 < N_NODES) ? g_norm_src[r0] : 0.f;
        float ns1 = (r1 < N_NODES) ? g_norm_src[r1] : 0.f;
#pragma unroll
        for (int ni = 0; ni < 8; ni++) {
            int c = warp_n * 64 + ni * 8 + 2 * qc;
            if (r0 < N_NODES)
                *(float2*)&h[(long)r0 * HIDDEN + c] =
                    make_float2(acc[mi][ni][0] * ns0, acc[mi][ni][1] * ns0);
            if (r1 < N_NODES)
                *(float2*)&h[(long)r1 * HIDDEN + c] =
                    make_float2(acc[mi][ni][2] * ns1, acc[mi][ni][3] * ns1);
        }
    }
}

// ---------------- aggregate layer 1 (CSR, no atomics) + relu + bias ----------
// one warp per dst node; lane covers 4 cols (float4); 4-deep gather pipeline
__global__ __launch_bounds__(256) void k_agg1(
    const float* __restrict__ h, const float* __restrict__ b1,
    float* __restrict__ h1)
{
    int node = blockIdx.x * 8 + (threadIdx.x >> 5);
    if (node >= N_NODES) return;
    int lane = threadIdx.x & 31;
    int beg = g_off[node];
    int end = g_off[node + 1];
    float4 acc = make_float4(0.f, 0.f, 0.f, 0.f);
    int i = beg;
    for (; i + 3 < end; i += 4) {
        int s0 = __ldg(&g_csrc[i]);
        int s1 = __ldg(&g_csrc[i + 1]);
        int s2 = __ldg(&g_csrc[i + 2]);
        int s3 = __ldg(&g_csrc[i + 3]);
        float4 v0 = *(const float4*)&h[(long)s0 * HIDDEN + lane * 4];
        float4 v1 = *(const float4*)&h[(long)s1 * HIDDEN + lane * 4];
        float4 v2 = *(const float4*)&h[(long)s2 * HIDDEN + lane * 4];
        float4 v3 = *(const float4*)&h[(long)s3 * HIDDEN + lane * 4];
        acc.x += (v0.x + v1.x) + (v2.x + v3.x);
        acc.y += (v0.y + v1.y) + (v2.y + v3.y);
        acc.z += (v0.z + v1.z) + (v2.z + v3.z);
        acc.w += (v0.w + v1.w) + (v2.w + v3.w);
    }
    for (; i < end; i++) {
        int s = __ldg(&g_csrc[i]);
        float4 v = *(const float4*)&h[(long)s * HIDDEN + lane * 4];
        acc.x += v.x; acc.y += v.y; acc.z += v.z; acc.w += v.w;
    }
    float nd = g_norm_dst[node];
    float4 b = *(const float4*)&b1[lane * 4];
    float4 o;
    o.x = fmaxf(acc.x * nd + b.x, 0.f);
    o.y = fmaxf(acc.y * nd + b.y, 0.f);
    o.z = fmaxf(acc.z * nd + b.z, 0.f);
    o.w = fmaxf(acc.w * nd + b.w, 0.f);
    *(float4*)&h1[(long)node * HIDDEN + lane * 4] = o;
}

// ---------------- GEMM2 (fp32): msg2 = (h1 * ns) @ W2  [N x 128]x[128 x 41] --
#define G2_ROWS 32
#define CPAD 44
__global__ __launch_bounds__(128) void k_gemm2(
    const float* __restrict__ h1, const float* __restrict__ W2,
    float* __restrict__ msg)
{
    __shared__ float Hs[G2_ROWS][HIDDEN + 1];
    __shared__ float Ws[HIDDEN][CPAD];
    const int tid = threadIdx.x;
    const int row0 = blockIdx.x * G2_ROWS;

    // W2: 128x41 -> padded 128x44 (plain indexing; 44 iters/thread, cheap)
    for (int i = tid; i < HIDDEN * CPAD; i += 128) {
        int k = i / CPAD, c = i % CPAD;
        Ws[k][c] = (c < N_CLS) ? __ldg(&W2[k * N_CLS + c]) : 0.f;
    }
    for (int i = tid; i < G2_ROWS * (HIDDEN / 4); i += 128) {
        int r = i >> 5;                           // /(HIDDEN/4)=32
        int k4 = (i & 31) * 4;
        int gr = row0 + r;
        float4 v = make_float4(0.f, 0.f, 0.f, 0.f);
        float nsv = 0.f;
        if (gr < N_NODES) {
            v = *(const float4*)&h1[(long)gr * HIDDEN + k4];
            nsv = g_norm_src[gr];
        }
        Hs[r][k4 + 0] = v.x * nsv;
        Hs[r][k4 + 1] = v.y * nsv;
        Hs[r][k4 + 2] = v.z * nsv;
        Hs[r][k4 + 3] = v.w * nsv;
    }
    __syncthreads();

    const int r  = tid & 31;
    const int c0 = (tid >> 5) * 11;
    float acc[11];
#pragma unroll
    for (int j = 0; j < 11; j++) acc[j] = 0.f;
#pragma unroll 4
    for (int k = 0; k < HIDDEN; k++) {
        float hk = Hs[r][k];
#pragma unroll
        for (int j = 0; j < 11; j++) acc[j] += hk * Ws[k][c0 + j];
    }
    int gr = row0 + r;
    if (gr < N_NODES) {
        float* mp = &msg[(long)gr * N_CLS];
#pragma unroll
        for (int j = 0; j < 11; j++) {
            int c = c0 + j;
            if (c < N_CLS) mp[c] = acc[j];
        }
    }
}

// ---------------- aggregate layer 2 (CSR) + dst-norm + bias -> out -----------
__global__ __launch_bounds__(256) void k_agg2(
    const float* __restrict__ msg, const float* __restrict__ b2,
    float* __restrict__ out)
{
    int node = blockIdx.x * 8 + (threadIdx.x >> 5);
    if (node >= N_NODES) return;
    int lane = threadIdx.x & 31;
    int beg = g_off[node];
    int end = g_off[node + 1];
    bool hi = (lane < N_CLS - 32);
    float a0 = 0.f, a1 = 0.f;
    int i = beg;
    for (; i + 3 < end; i += 4) {
        int s0 = __ldg(&g_csrc[i]);
        int s1 = __ldg(&g_csrc[i + 1]);
        int s2 = __ldg(&g_csrc[i + 2]);
        int s3 = __ldg(&g_csrc[i + 3]);
        const float* mp0 = &msg[(long)s0 * N_CLS];
        const float* mp1 = &msg[(long)s1 * N_CLS];
        const float* mp2 = &msg[(long)s2 * N_CLS];
        const float* mp3 = &msg[(long)s3 * N_CLS];
        a0 += (mp0[lane] + mp1[lane]) + (mp2[lane] + mp3[lane]);
        if (hi) a1 += (mp0[lane + 32] + mp1[lane + 32]) + (mp2[lane + 32] + mp3[lane + 32]);
    }
    for (; i < end; i++) {
        int s = __ldg(&g_csrc[i]);
        const float* mp = &msg[(long)s * N_CLS];
        a0 += mp[lane];
        if (hi) a1 += mp[lane + 32];
    }
    float nd = g_norm_dst[node];
    float* op = &out[(long)node * N_CLS];
    op[lane] = a0 * nd + b2[lane];
    if (hi) op[lane + 32] = a1 * nd + b2[lane + 32];
}

// =============================================================================
extern "C" void kernel_launch(void* const* d_in, const int* in_sizes, int n_in,
                              void* d_out, int out_size) {
    const float* x   = (const float*)d_in[0];
    const int* esrc  = (const int*)d_in[1];
    const int* edst  = (const int*)d_in[2];
    const float* W1  = (const float*)d_in[3];
    const float* b1  = (const float*)d_in[4];
    const float* W2  = (const float*)d_in[5];
    const float* b2  = (const float*)d_in[6];
    float* out = (float*)d_out;

    float *h, *h1, *msg2;
    cudaGetSymbolAddress((void**)&h, g_h);
    cudaGetSymbolAddress((void**)&h1, g_h1);
    cudaGetSymbolAddress((void**)&msg2, g_msg2);

    // allow 57KB dynamic smem for the 3-stage GEMM1 pipeline (idempotent)
    cudaFuncSetAttribute(k_gemm1, cudaFuncAttributeMaxDynamicSharedMemorySize,
                         G1_SMEM_BYTES);

    // ---- graph preprocessing (degrees, norms, CSR by dst) ----
    k_init<<<(N_NODES + 255) / 256, 256>>>();
    k_degrees<<<(N_EDGES / 2 + 255) / 256, 256>>>(esrc, edst);
    k_norms<<<(N_NODES + 255) / 256, 256>>>();
    k_scan<<<1, SCAN_T>>>();
    k_fill<<<(N_EDGES + 255) / 256, 256>>>(esrc, edst);

    // ---- layer 1 ----
    k_gemm1<<<(N_NODES + BM - 1) / BM, 256, G1_SMEM_BYTES>>>(x, W1, h);
    k_agg1<<<(N_NODES + 7) / 8, 256>>>(h, b1, h1);

    // ---- layer 2 ----
    k_gemm2<<<(N_NODES + G2_ROWS - 1) / G2_ROWS, 128>>>(h1, W2, msg2);
    k_agg2<<<(N_NODES + 7) / 8, 256>>>(msg2, b2, out);
}

// round 12
// speedup vs baseline: 1.4200x; 1.4200x over previous
#include <cuda_runtime.h>
#include <cuda_bf16.h>

#define N_NODES 100000
#define N_EDGES 1600000
#define N_FEAT  602
#define HIDDEN  128
#define N_CLS   41

// ---------------- scratch (static device globals; no runtime alloc) ----------
__device__ float g_h[(long)N_NODES * HIDDEN];      // GEMM1 output (pre-agg messages)
__device__ float g_h1[(long)N_NODES * HIDDEN];     // layer-1 output (post relu)
__device__ float g_msg2[(long)N_NODES * N_CLS];    // layer-2 projected messages
__device__ float g_norm_src[N_NODES];
__device__ float g_norm_dst[N_NODES];
__device__ int   g_deg_src[N_NODES];
__device__ int   g_deg_dst[N_NODES];
__device__ int   g_off[N_NODES + 1];               // CSR row offsets (by dst)
__device__ int   g_cursor[N_NODES];
__device__ int   g_csrc[N_EDGES];                  // src node per CSR slot

#define SCB 512
#define NSCB ((N_NODES + SCB - 1) / SCB)           // 196
__device__ int g_blksum[NSCB];
__device__ int g_blkoff[NSCB];

// ---------------- helpers ----------------------------------------------------
__device__ __forceinline__ unsigned f2tf(float f) {
    unsigned u;
    asm("cvt.rna.tf32.f32 %0, %1;" : "=r"(u) : "f"(f));
    return u;
}

__device__ __forceinline__ void mma_tf32(float d[4], const unsigned a[4], const unsigned b[2]) {
    asm volatile(
        "mma.sync.aligned.m16n8k8.row.col.f32.tf32.tf32.f32 "
        "{%0,%1,%2,%3}, {%4,%5,%6,%7}, {%8,%9}, {%0,%1,%2,%3};"
        : "+f"(d[0]), "+f"(d[1]), "+f"(d[2]), "+f"(d[3])
        : "r"(a[0]), "r"(a[1]), "r"(a[2]), "r"(a[3]),
          "r"(b[0]), "r"(b[1]));
}

__device__ __forceinline__ void cp_async8(unsigned smem_addr, const void* gptr, int src_bytes) {
    asm volatile("cp.async.ca.shared.global [%0], [%1], 8, %2;\n"
                 :: "r"(smem_addr), "l"(gptr), "r"(src_bytes));
}
__device__ __forceinline__ void cp_async16(unsigned smem_addr, const void* gptr, int src_bytes) {
    asm volatile("cp.async.ca.shared.global [%0], [%1], 16, %2;\n"
                 :: "r"(smem_addr), "l"(gptr), "r"(src_bytes));
}
__device__ __forceinline__ void cp_commit() {
    asm volatile("cp.async.commit_group;\n");
}
template<int N>
__device__ __forceinline__ void cp_wait() {
    asm volatile("cp.async.wait_group %0;\n" :: "n"(N));
}

// ---------------- init / degrees / norms -------------------------------------
__global__ void k_init() {
    int i = blockIdx.x * blockDim.x + threadIdx.x;
    if (i < N_NODES) { g_deg_src[i] = 0; g_deg_dst[i] = 0; }
}

__global__ void k_degrees(const int* __restrict__ src, const int* __restrict__ dst) {
    int i = blockIdx.x * blockDim.x + threadIdx.x;
    int e0 = i * 2;
    if (e0 < N_EDGES) {
        atomicAdd(&g_deg_src[__ldg(&src[e0])], 1);
        atomicAdd(&g_deg_dst[__ldg(&dst[e0])], 1);
    }
    int e1 = e0 + 1;
    if (e1 < N_EDGES) {
        atomicAdd(&g_deg_src[__ldg(&src[e1])], 1);
        atomicAdd(&g_deg_dst[__ldg(&dst[e1])], 1);
    }
}

__global__ void k_norms() {
    int i = blockIdx.x * blockDim.x + threadIdx.x;
    if (i < N_NODES) {
        g_norm_src[i] = rsqrtf((float)max(g_deg_src[i], 1));
        g_norm_dst[i] = rsqrtf((float)max(g_deg_dst[i], 1));
    }
}

// ---------------- 3-phase parallel exclusive scan of deg_dst -----------------
// A: per-block local exclusive scan (196 blocks x 512 thr) -> g_off (local), g_blksum
__global__ __launch_bounds__(SCB) void k_scan_blk() {
    __shared__ int sh[SCB];
    int b = blockIdx.x, t = threadIdx.x;
    int i = b * SCB + t;
    int v = (i < N_NODES) ? g_deg_dst[i] : 0;
    sh[t] = v;
    __syncthreads();
    for (int off = 1; off < SCB; off <<= 1) {
        int u = (t >= off) ? sh[t - off] : 0;
        __syncthreads();
        sh[t] += u;
        __syncthreads();
    }
    if (i < N_NODES) g_off[i] = sh[t] - v;       // exclusive, block-local
    if (t == SCB - 1) g_blksum[b] = sh[t];
}

// B: scan the 196 block sums (1 block, 256 threads)
__global__ __launch_bounds__(256) void k_scan_top() {
    __shared__ int sh[256];
    int t = threadIdx.x;
    int v = (t < NSCB) ? g_blksum[t] : 0;
    sh[t] = v;
    __syncthreads();
    for (int off = 1; off < 256; off <<= 1) {
        int u = (t >= off) ? sh[t - off] : 0;
        __syncthreads();
        sh[t] += u;
        __syncthreads();
    }
    if (t < NSCB) g_blkoff[t] = sh[t] - v;       // exclusive block offset
    if (t == 0) g_off[N_NODES] = N_EDGES;        // total degree == edge count
}

// C: add block offsets; materialize cursors
__global__ void k_scan_add() {
    int i = blockIdx.x * blockDim.x + threadIdx.x;
    if (i < N_NODES) {
        int v = g_off[i] + g_blkoff[i / SCB];
        g_off[i] = v;
        g_cursor[i] = v;
    }
}

__global__ void k_fill(const int* __restrict__ src, const int* __restrict__ dst) {
    int i = blockIdx.x * blockDim.x + threadIdx.x;
    if (i < N_EDGES) {
        int pos = atomicAdd(&g_cursor[__ldg(&dst[i])], 1);
        g_csrc[pos] = __ldg(&src[i]);
    }
}

// ---------------- GEMM1 (tf32 mma + 3-stage cp.async pipeline) ---------------
// h = (x @ W1) * norm_src[row]  (norm folded into epilogue)
// 128x128x16 tile, 8 warps (4M x 2N), warp tile 32x64 = 2x8 m16n8k8 per k8.
// As[m][k] stride 20 (frag banks 20*qr+qc all distinct mod 32)
// Bs[k][n] stride 136 (frag banks 8*qc+qr all distinct mod 32)
#define BM 128
#define BN 128
#define BK 16
#define NT ((N_FEAT + BK - 1) / BK)   // 38
#define ASTRIDE (BK + 4)              // 20
#define BSTRIDE (BN + 8)              // 136
#define STAGES 3
#define A_ELEMS (BM * ASTRIDE)        // 2560 floats/stage
#define B_ELEMS (BK * BSTRIDE)        // 2176 floats/stage
#define G1_SMEM_BYTES (STAGES * (A_ELEMS + B_ELEMS) * 4)   // 56832

__global__ __launch_bounds__(256) void k_gemm1(
    const float* __restrict__ x, const float* __restrict__ W1,
    float* __restrict__ h)
{
    extern __shared__ __align__(16) float smem[];
    float (*As)[BM][ASTRIDE] = (float(*)[BM][ASTRIDE])smem;
    float (*Bs)[BK][BSTRIDE] = (float(*)[BK][BSTRIDE])(smem + STAGES * A_ELEMS);

    const int tid  = threadIdx.x;
    const int wid  = tid >> 5;
    const int lane = tid & 31;
    const int warp_m = wid & 3;
    const int warp_n = wid >> 2;
    const int row0 = blockIdx.x * BM;
    const int qr = lane >> 2;              // 0..7
    const int qc = lane & 3;               // 0..3

    float acc[2][8][4];
#pragma unroll
    for (int mi = 0; mi < 2; mi++)
#pragma unroll
        for (int ni = 0; ni < 8; ni++)
#pragma unroll
            for (int j = 0; j < 4; j++) acc[mi][ni][j] = 0.f;

    auto issue_tile = [&](int t, int s) {
        int k0 = t * BK;
#pragma unroll
        for (int i = 0; i < 4; i++) {
            int p = tid + i * 256;
            int r = p >> 3;                // 0..127
            int k2 = (p & 7) * 2;          // 0,2,..,14 (even)
            int gr = row0 + r;
            int kk = k0 + k2;              // even; N_FEAT even -> tail is 8B or nothing
            int nb = (gr < N_NODES && kk < N_FEAT) ? 8 : 0;
            const float* gp = x + (long)min(gr, N_NODES - 1) * N_FEAT + min(kk, N_FEAT - 2);
            unsigned d = (unsigned)__cvta_generic_to_shared(&As[s][r][k2]);
            cp_async8(d, gp, nb);
        }
#pragma unroll
        for (int i = 0; i < 2; i++) {
            int q = tid + i * 256;
            int k = q >> 5;                // 0..15
            int c4 = (q & 31) * 4;
            int gk = k0 + k;
            int nb = (gk < N_FEAT) ? 16 : 0;
            const float* gp = W1 + (long)min(gk, N_FEAT - 1) * HIDDEN + c4;
            unsigned d = (unsigned)__cvta_generic_to_shared(&Bs[s][k][c4]);
            cp_async16(d, gp, nb);
        }
        cp_commit();
    };

    issue_tile(0, 0);
    issue_tile(1, 1);

    for (int t = 0; t < NT; t++) {
        int s = t % STAGES;
        // keep 2 tiles in flight; buffer (t+2)%3 drained by end-of-(t-1) barrier
        if (t + 2 < NT) { issue_tile(t + 2, (t + 2) % STAGES); cp_wait<2>(); }
        else if (t + 1 < NT) { cp_wait<1>(); }
        else { cp_wait<0>(); }
        __syncthreads();

#pragma unroll
        for (int ks = 0; ks < BK; ks += 8) {
            unsigned bf[8][2];
#pragma unroll
            for (int ni = 0; ni < 8; ni++) {
                int n0 = warp_n * 64 + ni * 8;
                bf[ni][0] = f2tf(Bs[s][ks + qc][n0 + qr]);
                bf[ni][1] = f2tf(Bs[s][ks + qc + 4][n0 + qr]);
            }
#pragma unroll
            for (int mi = 0; mi < 2; mi++) {
                int m0 = warp_m * 32 + mi * 16;
                unsigned af[4];
                af[0] = f2tf(As[s][m0 + qr][ks + qc]);
                af[1] = f2tf(As[s][m0 + qr + 8][ks + qc]);
                af[2] = f2tf(As[s][m0 + qr][ks + qc + 4]);
                af[3] = f2tf(As[s][m0 + qr + 8][ks + qc + 4]);
#pragma unroll
                for (int ni = 0; ni < 8; ni++)
                    mma_tf32(acc[mi][ni], af, bf[ni]);
            }
        }
        __syncthreads();   // all reads of buffer s done before re-issue at t+1
    }

    // ---- epilogue: scale row by norm_src; c0,c1 @(qr,2qc), c2,c3 @(qr+8,2qc)
#pragma unroll
    for (int mi = 0; mi < 2; mi++) {
        int mbase = row0 + warp_m * 32 + mi * 16;
        int r0 = mbase + qr;
        int r1 = mbase + qr + 8;
        float ns0 = (r0 < N_NODES) ? g_norm_src[r0] : 0.f;
        float ns1 = (r1 < N_NODES) ? g_norm_src[r1] : 0.f;
#pragma unroll
        for (int ni = 0; ni < 8; ni++) {
            int c = warp_n * 64 + ni * 8 + 2 * qc;
            if (r0 < N_NODES)
                *(float2*)&h[(long)r0 * HIDDEN + c] =
                    make_float2(acc[mi][ni][0] * ns0, acc[mi][ni][1] * ns0);
            if (r1 < N_NODES)
                *(float2*)&h[(long)r1 * HIDDEN + c] =
                    make_float2(acc[mi][ni][2] * ns1, acc[mi][ni][3] * ns1);
        }
    }
}

// ---------------- aggregate layer 1 (CSR, no atomics) + relu + bias ----------
// one warp per dst node; lane covers 4 cols (float4); 4-deep gather pipeline
__global__ __launch_bounds__(256) void k_agg1(
    const float* __restrict__ h, const float* __restrict__ b1,
    float* __restrict__ h1)
{
    int node = blockIdx.x * 8 + (threadIdx.x >> 5);
    if (node >= N_NODES) return;
    int lane = threadIdx.x & 31;
    int beg = g_off[node];
    int end = g_off[node + 1];
    float4 acc = make_float4(0.f, 0.f, 0.f, 0.f);
    int i = beg;
    for (; i + 3 < end; i += 4) {
        int s0 = __ldg(&g_csrc[i]);
        int s1 = __ldg(&g_csrc[i + 1]);
        int s2 = __ldg(&g_csrc[i + 2]);
        int s3 = __ldg(&g_csrc[i + 3]);
        float4 v0 = *(const float4*)&h[(long)s0 * HIDDEN + lane * 4];
        float4 v1 = *(const float4*)&h[(long)s1 * HIDDEN + lane * 4];
        float4 v2 = *(const float4*)&h[(long)s2 * HIDDEN + lane * 4];
        float4 v3 = *(const float4*)&h[(long)s3 * HIDDEN + lane * 4];
        acc.x += (v0.x + v1.x) + (v2.x + v3.x);
        acc.y += (v0.y + v1.y) + (v2.y + v3.y);
        acc.z += (v0.z + v1.z) + (v2.z + v3.z);
        acc.w += (v0.w + v1.w) + (v2.w + v3.w);
    }
    for (; i < end; i++) {
        int s = __ldg(&g_csrc[i]);
        float4 v = *(const float4*)&h[(long)s * HIDDEN + lane * 4];
        acc.x += v.x; acc.y += v.y; acc.z += v.z; acc.w += v.w;
    }
    float nd = g_norm_dst[node];
    float4 b = *(const float4*)&b1[lane * 4];
    float4 o;
    o.x = fmaxf(acc.x * nd + b.x, 0.f);
    o.y = fmaxf(acc.y * nd + b.y, 0.f);
    o.z = fmaxf(acc.z * nd + b.z, 0.f);
    o.w = fmaxf(acc.w * nd + b.w, 0.f);
    *(float4*)&h1[(long)node * HIDDEN + lane * 4] = o;
}

// ---------------- GEMM2 (fp32): msg2 = (h1 * ns) @ W2  [N x 128]x[128 x 41] --
#define G2_ROWS 32
#define CPAD 44
__global__ __launch_bounds__(128) void k_gemm2(
    const float* __restrict__ h1, const float* __restrict__ W2,
    float* __restrict__ msg)
{
    __shared__ float Hs[G2_ROWS][HIDDEN + 1];
    __shared__ float Ws[HIDDEN][CPAD];
    const int tid = threadIdx.x;
    const int row0 = blockIdx.x * G2_ROWS;

    for (int i = tid; i < HIDDEN * CPAD; i += 128) {
        int k = i / CPAD, c = i % CPAD;
        Ws[k][c] = (c < N_CLS) ? __ldg(&W2[k * N_CLS + c]) : 0.f;
    }
    for (int i = tid; i < G2_ROWS * (HIDDEN / 4); i += 128) {
        int r = i >> 5;                           // /(HIDDEN/4)=32
        int k4 = (i & 31) * 4;
        int gr = row0 + r;
        float4 v = make_float4(0.f, 0.f, 0.f, 0.f);
        float nsv = 0.f;
        if (gr < N_NODES) {
            v = *(const float4*)&h1[(long)gr * HIDDEN + k4];
            nsv = g_norm_src[gr];
        }
        Hs[r][k4 + 0] = v.x * nsv;
        Hs[r][k4 + 1] = v.y * nsv;
        Hs[r][k4 + 2] = v.z * nsv;
        Hs[r][k4 + 3] = v.w * nsv;
    }
    __syncthreads();

    const int r  = tid & 31;
    const int c0 = (tid >> 5) * 11;
    float acc[11];
#pragma unroll
    for (int j = 0; j < 11; j++) acc[j] = 0.f;
#pragma unroll 4
    for (int k = 0; k < HIDDEN; k++) {
        float hk = Hs[r][k];
#pragma unroll
        for (int j = 0; j < 11; j++) acc[j] += hk * Ws[k][c0 + j];
    }
    int gr = row0 + r;
    if (gr < N_NODES) {
        float* mp = &msg[(long)gr * N_CLS];
#pragma unroll
        for (int j = 0; j < 11; j++) {
            int c = c0 + j;
            if (c < N_CLS) mp[c] = acc[j];
        }
    }
}

// ---------------- aggregate layer 2 (CSR) + dst-norm + bias -> out -----------
__global__ __launch_bounds__(256) void k_agg2(
    const float* __restrict__ msg, const float* __restrict__ b2,
    float* __restrict__ out)
{
    int node = blockIdx.x * 8 + (threadIdx.x >> 5);
    if (node >= N_NODES) return;
    int lane = threadIdx.x & 31;
    int beg = g_off[node];
    int end = g_off[node + 1];
    bool hi = (lane < N_CLS - 32);
    float a0 = 0.f, a1 = 0.f;
    int i = beg;
    for (; i + 3 < end; i += 4) {
        int s0 = __ldg(&g_csrc[i]);
        int s1 = __ldg(&g_csrc[i + 1]);
        int s2 = __ldg(&g_csrc[i + 2]);
        int s3 = __ldg(&g_csrc[i + 3]);
        const float* mp0 = &msg[(long)s0 * N_CLS];
        const float* mp1 = &msg[(long)s1 * N_CLS];
        const float* mp2 = &msg[(long)s2 * N_CLS];
        const float* mp3 = &msg[(long)s3 * N_CLS];
        a0 += (mp0[lane] + mp1[lane]) + (mp2[lane] + mp3[lane]);
        if (hi) a1 += (mp0[lane + 32] + mp1[lane + 32]) + (mp2[lane + 32] + mp3[lane + 32]);
    }
    for (; i < end; i++) {
        int s = __ldg(&g_csrc[i]);
        const float* mp = &msg[(long)s * N_CLS];
        a0 += mp[lane];
        if (hi) a1 += mp[lane + 32];
    }
    float nd = g_norm_dst[node];
    float* op = &out[(long)node * N_CLS];
    op[lane] = a0 * nd + b2[lane];
    if (hi) op[lane + 32] = a1 * nd + b2[lane + 32];
}

// =============================================================================
extern "C" void kernel_launch(void* const* d_in, const int* in_sizes, int n_in,
                              void* d_out, int out_size) {
    const float* x   = (const float*)d_in[0];
    const int* esrc  = (const int*)d_in[1];
    const int* edst  = (const int*)d_in[2];
    const float* W1  = (const float*)d_in[3];
    const float* b1  = (const float*)d_in[4];
    const float* W2  = (const float*)d_in[5];
    const float* b2  = (const float*)d_in[6];
    float* out = (float*)d_out;

    float *h, *h1, *msg2;
    cudaGetSymbolAddress((void**)&h, g_h);
    cudaGetSymbolAddress((void**)&h1, g_h1);
    cudaGetSymbolAddress((void**)&msg2, g_msg2);

    // allow 57KB dynamic smem for the 3-stage GEMM1 pipeline (idempotent)
    cudaFuncSetAttribute(k_gemm1, cudaFuncAttributeMaxDynamicSharedMemorySize,
                         G1_SMEM_BYTES);

    // ---- graph preprocessing (degrees, norms, parallel CSR scan) ----
    k_init<<<(N_NODES + 255) / 256, 256>>>();
    k_degrees<<<(N_EDGES / 2 + 255) / 256, 256>>>(esrc, edst);
    k_norms<<<(N_NODES + 255) / 256, 256>>>();
    k_scan_blk<<<NSCB, SCB>>>();
    k_scan_top<<<1, 256>>>();
    k_scan_add<<<(N_NODES + 255) / 256, 256>>>();
    k_fill<<<(N_EDGES + 255) / 256, 256>>>(esrc, edst);

    // ---- layer 1 ----
    k_gemm1<<<(N_NODES + BM - 1) / BM, 256, G1_SMEM_BYTES>>>(x, W1, h);
    k_agg1<<<(N_NODES + 7) / 8, 256>>>(h, b1, h1);

    // ---- layer 2 ----
    k_gemm2<<<(N_NODES + G2_ROWS - 1) / G2_ROWS, 128>>>(h1, W2, msg2);
    k_agg2<<<(N_NODES + 7) / 8, 256>>>(msg2, b2, out);
}

// round 16
// speedup vs baseline: 1.4283x; 1.0058x over previous
#include <cuda_runtime.h>
#include <cuda_bf16.h>

#define N_NODES 100000
#define N_EDGES 1600000
#define N_FEAT  602
#define HIDDEN  128
#define N_CLS   41

// ---------------- scratch (static device globals; no runtime alloc) ----------
__device__ float g_h[(long)N_NODES * HIDDEN];      // GEMM1 output (pre-agg messages)
__device__ float g_h1[(long)N_NODES * HIDDEN];     // layer-1 output (post relu)
__device__ float g_msg2[(long)N_NODES * N_CLS];    // layer-2 projected messages
__device__ float g_norm_src[N_NODES];
__device__ float g_norm_dst[N_NODES];
__device__ int   g_deg_src[N_NODES];
__device__ int   g_deg_dst[N_NODES];
__device__ int   g_off[N_NODES + 1];               // CSR row offsets (by dst)
__device__ int   g_cursor[N_NODES];
__device__ int   g_csrc[N_EDGES];                  // src node per CSR slot
__device__ unsigned g_w1tf[N_FEAT * HIDDEN];       // W1 pre-converted to tf32 bits (rna)

#define SCB 512
#define NSCB ((N_NODES + SCB - 1) / SCB)           // 196
__device__ int g_blksum[NSCB];
__device__ int g_blkoff[NSCB];

// ---------------- helpers ----------------------------------------------------
__device__ __forceinline__ unsigned f2tf(float f) {
    unsigned u;
    asm("cvt.rna.tf32.f32 %0, %1;" : "=r"(u) : "f"(f));
    return u;
}

__device__ __forceinline__ void mma_tf32(float d[4], const unsigned a[4], const unsigned b[2]) {
    asm volatile(
        "mma.sync.aligned.m16n8k8.row.col.f32.tf32.tf32.f32 "
        "{%0,%1,%2,%3}, {%4,%5,%6,%7}, {%8,%9}, {%0,%1,%2,%3};"
        : "+f"(d[0]), "+f"(d[1]), "+f"(d[2]), "+f"(d[3])
        : "r"(a[0]), "r"(a[1]), "r"(a[2]), "r"(a[3]),
          "r"(b[0]), "r"(b[1]));
}

__device__ __forceinline__ void cp_async8(unsigned smem_addr, const void* gptr, int src_bytes) {
    asm volatile("cp.async.ca.shared.global [%0], [%1], 8, %2;\n"
                 :: "r"(smem_addr), "l"(gptr), "r"(src_bytes));
}
__device__ __forceinline__ void cp_async16(unsigned smem_addr, const void* gptr, int src_bytes) {
    asm volatile("cp.async.ca.shared.global [%0], [%1], 16, %2;\n"
                 :: "r"(smem_addr), "l"(gptr), "r"(src_bytes));
}
__device__ __forceinline__ void cp_commit() {
    asm volatile("cp.async.commit_group;\n");
}
template<int N>
__device__ __forceinline__ void cp_wait() {
    asm volatile("cp.async.wait_group %0;\n" :: "n"(N));
}

// ---------------- W1 -> tf32 bits (rna), one-time ----------------------------
__global__ void k_cvtw1(const float* __restrict__ W1) {
    int i = blockIdx.x * blockDim.x + threadIdx.x;
    if (i < N_FEAT * HIDDEN) g_w1tf[i] = f2tf(W1[i]);
}

// ---------------- init / degrees -------------------------------------------
__global__ void k_init() {
    int i = blockIdx.x * blockDim.x + threadIdx.x;
    if (i < N_NODES) { g_deg_src[i] = 0; g_deg_dst[i] = 0; }
}

__global__ void k_degrees(const int* __restrict__ src, const int* __restrict__ dst) {
    int i = blockIdx.x * blockDim.x + threadIdx.x;
    int e0 = i * 2;
    if (e0 < N_EDGES) {
        atomicAdd(&g_deg_src[__ldg(&src[e0])], 1);
        atomicAdd(&g_deg_dst[__ldg(&dst[e0])], 1);
    }
    int e1 = e0 + 1;
    if (e1 < N_EDGES) {
        atomicAdd(&g_deg_src[__ldg(&src[e1])], 1);
        atomicAdd(&g_deg_dst[__ldg(&dst[e1])], 1);
    }
}

// ---------------- 3-phase parallel exclusive scan of deg_dst -----------------
__global__ __launch_bounds__(SCB) void k_scan_blk() {
    __shared__ int sh[SCB];
    int b = blockIdx.x, t = threadIdx.x;
    int i = b * SCB + t;
    int v = (i < N_NODES) ? g_deg_dst[i] : 0;
    sh[t] = v;
    __syncthreads();
    for (int off = 1; off < SCB; off <<= 1) {
        int u = (t >= off) ? sh[t - off] : 0;
        __syncthreads();
        sh[t] += u;
        __syncthreads();
    }
    if (i < N_NODES) g_off[i] = sh[t] - v;       // exclusive, block-local
    if (t == SCB - 1) g_blksum[b] = sh[t];
}

__global__ __launch_bounds__(256) void k_scan_top() {
    __shared__ int sh[256];
    int t = threadIdx.x;
    int v = (t < NSCB) ? g_blksum[t] : 0;
    sh[t] = v;
    __syncthreads();
    for (int off = 1; off < 256; off <<= 1) {
        int u = (t >= off) ? sh[t - off] : 0;
        __syncthreads();
        sh[t] += u;
        __syncthreads();
    }
    if (t < NSCB) g_blkoff[t] = sh[t] - v;       // exclusive block offset
    if (t == 0) g_off[N_NODES] = N_EDGES;        // total degree == edge count
}

// C: add block offsets; materialize cursors; compute norms (fused)
__global__ void k_scan_add() {
    int i = blockIdx.x * blockDim.x + threadIdx.x;
    if (i < N_NODES) {
        int v = g_off[i] + g_blkoff[i / SCB];
        g_off[i] = v;
        g_cursor[i] = v;
        g_norm_src[i] = rsqrtf((float)max(g_deg_src[i], 1));
        g_norm_dst[i] = rsqrtf((float)max(g_deg_dst[i], 1));
    }
}

__global__ void k_fill(const int* __restrict__ src, const int* __restrict__ dst) {
    int i = blockIdx.x * blockDim.x + threadIdx.x;
    if (i < N_EDGES) {
        int pos = atomicAdd(&g_cursor[__ldg(&dst[i])], 1);
        g_csrc[pos] = __ldg(&src[i]);
    }
}

// ---------------- GEMM1 (tf32 mma + 3-stage cp.async pipeline) ---------------
// h = (x @ W1) * norm_src[row]  (norm folded into epilogue)
// 128x128x16 tile, 8 warps (4M x 2N), warp tile 32x64 = 2x8 m16n8k8 per k8.
// As[m][k] stride 20 (frag banks 20*qr+qc all distinct mod 32)
// Bs[k][n] stride 136 (frag banks 8*qc+qr all distinct mod 32)
// B tiles pre-converted to tf32 (g_w1tf); A converted rna at fragment load.
#define BM 128
#define BN 128
#define BK 16
#define NT ((N_FEAT + BK - 1) / BK)   // 38
#define ASTRIDE (BK + 4)              // 20
#define BSTRIDE (BN + 8)              // 136
#define STAGES 3
#define A_ELEMS (BM * ASTRIDE)        // 2560 floats/stage
#define B_ELEMS (BK * BSTRIDE)        // 2176 words/stage
#define G1_SMEM_BYTES (STAGES * (A_ELEMS + B_ELEMS) * 4)   // 56832

__global__ __launch_bounds__(256) void k_gemm1(
    const float* __restrict__ x,
    float* __restrict__ h)
{
    extern __shared__ __align__(16) float smem[];
    float    (*As)[BM][ASTRIDE] = (float(*)[BM][ASTRIDE])smem;
    unsigned (*Bs)[BK][BSTRIDE] = (unsigned(*)[BK][BSTRIDE])(smem + STAGES * A_ELEMS);

    const int tid  = threadIdx.x;
    const int wid  = tid >> 5;
    const int lane = tid & 31;
    const int warp_m = wid & 3;
    const int warp_n = wid >> 2;
    const int row0 = blockIdx.x * BM;
    const int qr = lane >> 2;              // 0..7
    const int qc = lane & 3;               // 0..3

    float acc[2][8][4];
#pragma unroll
    for (int mi = 0; mi < 2; mi++)
#pragma unroll
        for (int ni = 0; ni < 8; ni++)
#pragma unroll
            for (int j = 0; j < 4; j++) acc[mi][ni][j] = 0.f;

    auto issue_tile = [&](int t, int s) {
        int k0 = t * BK;
#pragma unroll
        for (int i = 0; i < 4; i++) {
            int p = tid + i * 256;
            int r = p >> 3;                // 0..127
            int k2 = (p & 7) * 2;          // 0,2,..,14 (even)
            int gr = row0 + r;
            int kk = k0 + k2;              // even; N_FEAT even -> tail is 8B or nothing
            int nb = (gr < N_NODES && kk < N_FEAT) ? 8 : 0;
            const float* gp = x + (long)min(gr, N_NODES - 1) * N_FEAT + min(kk, N_FEAT - 2);
            unsigned d = (unsigned)__cvta_generic_to_shared(&As[s][r][k2]);
            cp_async8(d, gp, nb);
        }
#pragma unroll
        for (int i = 0; i < 2; i++) {
            int q = tid + i * 256;
            int k = q >> 5;                // 0..15
            int c4 = (q & 31) * 4;
            int gk = k0 + k;
            int nb = (gk < N_FEAT) ? 16 : 0;
            const unsigned* gp = g_w1tf + (long)min(gk, N_FEAT - 1) * HIDDEN + c4;
            unsigned d = (unsigned)__cvta_generic_to_shared(&Bs[s][k][c4]);
            cp_async16(d, gp, nb);
        }
        cp_commit();
    };

    issue_tile(0, 0);
    issue_tile(1, 1);

    for (int t = 0; t < NT; t++) {
        int s = t % STAGES;
        // keep 2 tiles in flight; buffer (t+2)%3 drained by end-of-(t-1) barrier
        if (t + 2 < NT) { issue_tile(t + 2, (t + 2) % STAGES); cp_wait<2>(); }
        else if (t + 1 < NT) { cp_wait<1>(); }
        else { cp_wait<0>(); }
        __syncthreads();

#pragma unroll
        for (int ks = 0; ks < BK; ks += 8) {
            unsigned bf[8][2];
#pragma unroll
            for (int ni = 0; ni < 8; ni++) {
                int n0 = warp_n * 64 + ni * 8;
                bf[ni][0] = Bs[s][ks + qc][n0 + qr];        // pre-converted tf32
                bf[ni][1] = Bs[s][ks + qc + 4][n0 + qr];
            }
#pragma unroll
            for (int mi = 0; mi < 2; mi++) {
                int m0 = warp_m * 32 + mi * 16;
                unsigned af[4];
                af[0] = f2tf(As[s][m0 + qr][ks + qc]);      // rna convert (A only)
                af[1] = f2tf(As[s][m0 + qr + 8][ks + qc]);
                af[2] = f2tf(As[s][m0 + qr][ks + qc + 4]);
                af[3] = f2tf(As[s][m0 + qr + 8][ks + qc + 4]);
#pragma unroll
                for (int ni = 0; ni < 8; ni++)
                    mma_tf32(acc[mi][ni], af, bf[ni]);
            }
        }
        __syncthreads();   // all reads of buffer s done before re-issue at t+1
    }

    // ---- epilogue: scale row by norm_src; c0,c1 @(qr,2qc), c2,c3 @(qr+8,2qc)
#pragma unroll
    for (int mi = 0; mi < 2; mi++) {
        int mbase = row0 + warp_m * 32 + mi * 16;
        int r0 = mbase + qr;
        int r1 = mbase + qr + 8;
        float ns0 = (r0 < N_NODES) ? g_norm_src[r0] : 0.f;
        float ns1 = (r1 < N_NODES) ? g_norm_src[r1] : 0.f;
#pragma unroll
        for (int ni = 0; ni < 8; ni++) {
            int c = warp_n * 64 + ni * 8 + 2 * qc;
            if (r0 < N_NODES)
                *(float2*)&h[(long)r0 * HIDDEN + c] =
                    make_float2(acc[mi][ni][0] * ns0, acc[mi][ni][1] * ns0);
            if (r1 < N_NODES)
                *(float2*)&h[(long)r1 * HIDDEN + c] =
                    make_float2(acc[mi][ni][2] * ns1, acc[mi][ni][3] * ns1);
        }
    }
}

// ---------------- aggregate layer 1 (CSR, no atomics) + relu + bias ----------
// one warp per dst node; lane covers 4 cols (float4); 4-deep gather pipeline
__global__ __launch_bounds__(256) void k_agg1(
    const float* __restrict__ h, const float* __restrict__ b1,
    float* __restrict__ h1)
{
    int node = blockIdx.x * 8 + (threadIdx.x >> 5);
    if (node >= N_NODES) return;
    int lane = threadIdx.x & 31;
    int beg = g_off[node];
    int end = g_off[node + 1];
    float4 acc = make_float4(0.f, 0.f, 0.f, 0.f);
    int i = beg;
    for (; i + 3 < end; i += 4) {
        int s0 = __ldg(&g_csrc[i]);
        int s1 = __ldg(&g_csrc[i + 1]);
        int s2 = __ldg(&g_csrc[i + 2]);
        int s3 = __ldg(&g_csrc[i + 3]);
        float4 v0 = *(const float4*)&h[(long)s0 * HIDDEN + lane * 4];
        float4 v1 = *(const float4*)&h[(long)s1 * HIDDEN + lane * 4];
        float4 v2 = *(const float4*)&h[(long)s2 * HIDDEN + lane * 4];
        float4 v3 = *(const float4*)&h[(long)s3 * HIDDEN + lane * 4];
        acc.x += (v0.x + v1.x) + (v2.x + v3.x);
        acc.y += (v0.y + v1.y) + (v2.y + v3.y);
        acc.z += (v0.z + v1.z) + (v2.z + v3.z);
        acc.w += (v0.w + v1.w) + (v2.w + v3.w);
    }
    for (; i < end; i++) {
        int s = __ldg(&g_csrc[i]);
        float4 v = *(const float4*)&h[(long)s * HIDDEN + lane * 4];
        acc.x += v.x; acc.y += v.y; acc.z += v.z; acc.w += v.w;
    }
    float nd = g_norm_dst[node];
    float4 b = *(const float4*)&b1[lane * 4];
    float4 o;
    o.x = fmaxf(acc.x * nd + b.x, 0.f);
    o.y = fmaxf(acc.y * nd + b.y, 0.f);
    o.z = fmaxf(acc.z * nd + b.z, 0.f);
    o.w = fmaxf(acc.w * nd + b.w, 0.f);
    *(float4*)&h1[(long)node * HIDDEN + lane * 4] = o;
}

// ---------------- GEMM2 (fp32): msg2 = (h1 * ns) @ W2  [N x 128]x[128 x 41] --
#define G2_ROWS 32
#define CPAD 44
__global__ __launch_bounds__(128) void k_gemm2(
    const float* __restrict__ h1, const float* __restrict__ W2,
    float* __restrict__ msg)
{
    __shared__ float Hs[G2_ROWS][HIDDEN + 1];
    __shared__ float Ws[HIDDEN][CPAD];
    const int tid = threadIdx.x;
    const int row0 = blockIdx.x * G2_ROWS;

    for (int i = tid; i < HIDDEN * CPAD; i += 128) {
        int k = i / CPAD, c = i % CPAD;
        Ws[k][c] = (c < N_CLS) ? __ldg(&W2[k * N_CLS + c]) : 0.f;
    }
    for (int i = tid; i < G2_ROWS * (HIDDEN / 4); i += 128) {
        int r = i >> 5;                           // /(HIDDEN/4)=32
        int k4 = (i & 31) * 4;
        int gr = row0 + r;
        float4 v = make_float4(0.f, 0.f, 0.f, 0.f);
        float nsv = 0.f;
        if (gr < N_NODES) {
            v = *(const float4*)&h1[(long)gr * HIDDEN + k4];
            nsv = g_norm_src[gr];
        }
        Hs[r][k4 + 0] = v.x * nsv;
        Hs[r][k4 + 1] = v.y * nsv;
        Hs[r][k4 + 2] = v.z * nsv;
        Hs[r][k4 + 3] = v.w * nsv;
    }
    __syncthreads();

    const int r  = tid & 31;
    const int c0 = (tid >> 5) * 11;
    float acc[11];
#pragma unroll
    for (int j = 0; j < 11; j++) acc[j] = 0.f;
#pragma unroll 4
    for (int k = 0; k < HIDDEN; k++) {
        float hk = Hs[r][k];
#pragma unroll
        for (int j = 0; j < 11; j++) acc[j] += hk * Ws[k][c0 + j];
    }
    int gr = row0 + r;
    if (gr < N_NODES) {
        float* mp = &msg[(long)gr * N_CLS];
#pragma unroll
        for (int j = 0; j < 11; j++) {
            int c = c0 + j;
            if (c < N_CLS) mp[c] = acc[j];
        }
    }
}

// ---------------- aggregate layer 2 (CSR) + dst-norm + bias -> out -----------
__global__ __launch_bounds__(256) void k_agg2(
    const float* __restrict__ msg, const float* __restrict__ b2,
    float* __restrict__ out)
{
    int node = blockIdx.x * 8 + (threadIdx.x >> 5);
    if (node >= N_NODES) return;
    int lane = threadIdx.x & 31;
    int beg = g_off[node];
    int end = g_off[node + 1];
    bool hi = (lane < N_CLS - 32);
    float a0 = 0.f, a1 = 0.f;
    int i = beg;
    for (; i + 3 < end; i += 4) {
        int s0 = __ldg(&g_csrc[i]);
        int s1 = __ldg(&g_csrc[i + 1]);
        int s2 = __ldg(&g_csrc[i + 2]);
        int s3 = __ldg(&g_csrc[i + 3]);
        const float* mp0 = &msg[(long)s0 * N_CLS];
        const float* mp1 = &msg[(long)s1 * N_CLS];
        const float* mp2 = &msg[(long)s2 * N_CLS];
        const float* mp3 = &msg[(long)s3 * N_CLS];
        a0 += (mp0[lane] + mp1[lane]) + (mp2[lane] + mp3[lane]);
        if (hi) a1 += (mp0[lane + 32] + mp1[lane + 32]) + (mp2[lane + 32] + mp3[lane + 32]);
    }
    for (; i < end; i++) {
        int s = __ldg(&g_csrc[i]);
        const float* mp = &msg[(long)s * N_CLS];
        a0 += mp[lane];
        if (hi) a1 += mp[lane + 32];
    }
    float nd = g_norm_dst[node];
    float* op = &out[(long)node * N_CLS];
    op[lane] = a0 * nd + b2[lane];
    if (hi) op[lane + 32] = a1 * nd + b2[lane + 32];
}

// =============================================================================
extern "C" void kernel_launch(void* const* d_in, const int* in_sizes, int n_in,
                              void* d_out, int out_size) {
    const float* x   = (const float*)d_in[0];
    const int* esrc  = (const int*)d_in[1];
    const int* edst  = (const int*)d_in[2];
    const float* W1  = (const float*)d_in[3];
    const float* b1  = (const float*)d_in[4];
    const float* W2  = (const float*)d_in[5];
    const float* b2  = (const float*)d_in[6];
    float* out = (float*)d_out;

    float *h, *h1, *msg2;
    cudaGetSymbolAddress((void**)&h, g_h);
    cudaGetSymbolAddress((void**)&h1, g_h1);
    cudaGetSymbolAddress((void**)&msg2, g_msg2);

    // allow 57KB dynamic smem for the 3-stage GEMM1 pipeline (idempotent)
    cudaFuncSetAttribute(k_gemm1, cudaFuncAttributeMaxDynamicSharedMemorySize,
                         G1_SMEM_BYTES);

    // ---- one-time W1 tf32 conversion (independent; overlaps graph prep) ----
    k_cvtw1<<<(N_FEAT * HIDDEN + 255) / 256, 256>>>(W1);

    // ---- graph preprocessing (degrees, parallel CSR scan, norms fused) ----
    k_init<<<(N_NODES + 255) / 256, 256>>>();
    k_degrees<<<(N_EDGES / 2 + 255) / 256, 256>>>(esrc, edst);
    k_scan_blk<<<NSCB, SCB>>>();
    k_scan_top<<<1, 256>>>();
    k_scan_add<<<(N_NODES + 255) / 256, 256>>>();
    k_fill<<<(N_EDGES + 255) / 256, 256>>>(esrc, edst);

    // ---- layer 1 ----
    k_gemm1<<<(N_NODES + BM - 1) / BM, 256, G1_SMEM_BYTES>>>(x, h);
    k_agg1<<<(N_NODES + 7) / 8, 256>>>(h, b1, h1);

    // ---- layer 2 ----
    k_gemm2<<<(N_NODES + G2_ROWS - 1) / G2_ROWS, 128>>>(h1, W2, msg2);
    k_agg2<<<(N_NODES + 7) / 8, 256>>>(msg2, b2, out);
}